// round 2
// baseline (speedup 1.0000x reference)
#include <cuda_runtime.h>
#include <cstdint>

// ---------------- problem constants ----------------
#define B_TOT   16384
#define T_HOR   128
#define F_IN    29
#define K_HID   512
#define BTILE   128
#define NTH     256
#define NCTAS   (B_TOT / BTILE)     // 128, exact
#define TF_STR  (T_HOR * F_IN)      // 3712 floats per batch row

// ---------------- shared memory layout ----------------
// Bsm: 4 k-chunks x 512 cols x 4 pairs of float2 = 8192 float2 = 64KB
// cps: 256 col-pairs x 8 floats (wf0,wf0',wf1,wf1',wf2,wf2',w2,w2') = 8KB
#define SM_B_F2   8192
#define SM_CP_OFF (SM_B_F2 * 8)           // 65536 bytes
#define SM_TOTAL  (SM_CP_OFF + 512 * 16 / 2 + 0 + 8192)  // 65536 + 8192 = 73728

typedef unsigned long long ull;

static __device__ __forceinline__ uint32_t tf32r(float x) {
    uint32_t r;
    asm("cvt.rna.tf32.f32 %0, %1;" : "=r"(r) : "f"(x));
    return r;
}

// tanh(z) = 1 - 2/(1 + e^{2z});  e^{2z} = 2^{z * 2*log2(e)}.  ~1e-6 accurate.
static __device__ __forceinline__ float fast_tanh(float z) {
    float e, r;
    asm("ex2.approx.f32 %0, %1;" : "=f"(e) : "f"(z * 2.8853900817779268f));
    asm("rcp.approx.f32 %0, %1;" : "=f"(r) : "f"(e + 1.0f));
    return fmaf(-2.0f, r, 1.0f);
}

#define PACK2(d, lo, hi) \
    asm("mov.b64 %0, {%1, %2};" : "=l"(d) : "r"(__float_as_uint(lo)), "r"(__float_as_uint(hi)))
#define UNPACK2(lo, hi, s) \
    asm("mov.b64 {%0, %1}, %2;" : "=r"(lo), "=r"(hi) : "l"(s))
#define FMA2(d, a, b, c) \
    asm("fma.rn.f32x2 %0, %1, %2, %3;" : "=l"(d) : "l"(a), "l"(b), "l"(c))

#define MMA_TF32(d0, d1, d2, d3, a0, a1, a2, a3, b0, b1)                       \
    asm volatile(                                                              \
        "mma.sync.aligned.m16n8k8.row.col.f32.tf32.tf32.f32 "                  \
        "{%0,%1,%2,%3}, {%4,%5,%6,%7}, {%8,%9}, {%0,%1,%2,%3};"                \
        : "+f"(d0), "+f"(d1), "+f"(d2), "+f"(d3)                               \
        : "r"(a0), "r"(a1), "r"(a2), "r"(a3), "r"(b0), "r"(b1))

// Load the A fragments (16 tf32 regs) for time step t.
// Rows: rA (=l/4 within the warp tile) and rA+8. Cols: kc*8 + lq, kc*8 + lq + 4.
// Col 29 = 1.0 (bias row folded into the GEMM), cols 30/31 = 0.
static __device__ __forceinline__ void loadA(uint32_t a[16], const float* __restrict__ pA,
                                             const float* __restrict__ pB, int t, int lq,
                                             bool valid) {
    if (!valid) {
        #pragma unroll
        for (int i = 0; i < 16; ++i) a[i] = 0u;
        return;
    }
    const float* xA = pA + t * F_IN;
    const float* xB = pB + t * F_IN;
    #pragma unroll
    for (int kc = 0; kc < 4; ++kc) {
        const int c0 = kc * 8 + lq;          // <= 27, always a real X column
        a[kc * 4 + 0] = tf32r(__ldg(xA + c0));
        a[kc * 4 + 1] = tf32r(__ldg(xB + c0));
        if (kc < 3) {
            const int c1 = c0 + 4;           // <= 23
            a[kc * 4 + 2] = tf32r(__ldg(xA + c1));
            a[kc * 4 + 3] = tf32r(__ldg(xB + c1));
        } else {
            const int c1 = c0 + 4;           // 28..31
            float vA, vB;
            if (c1 < F_IN)      { vA = __ldg(xA + c1); vB = __ldg(xB + c1); }
            else if (c1 == F_IN) { vA = 1.0f; vB = 1.0f; }
            else                 { vA = 0.0f; vB = 0.0f; }
            a[14] = tf32r(vA);
            a[15] = tf32r(vB);
        }
    }
}

__global__ void __launch_bounds__(NTH)
narx_kernel(const float* __restrict__ X, const float* __restrict__ y0,
            const float* __restrict__ W1, const float* __restrict__ b1,
            const float* __restrict__ W2, const float* __restrict__ b2,
            float* __restrict__ out)
{
    extern __shared__ char smem[];
    float2* __restrict__ Bsm = (float2*)smem;
    float*  __restrict__ cps = (float*)(smem + SM_CP_OFF);
    const float4* __restrict__ cp4 = (const float4*)cps;

    const int tid  = threadIdx.x;
    const int w    = tid >> 5;
    const int lane = tid & 31;
    const int lq   = lane & 3;       // quad lane (k / col-pair selector)
    const int lg   = lane >> 2;      // group (row / n selector)

    // --- stage B operand: W1 rows 0-28, row 29 = b1 (bias), rows 30/31 = 0 ---
    // Layout: float2 idx = kc*2048 + col*4 + p  holds (W[kc*8+p][col], W[kc*8+p+4][col]).
    // Fragment fetch is then Bsm[kc*2048 + nt*32 + lane] -> fully coalesced LDS.64.
    for (int idx = tid; idx < SM_B_F2; idx += NTH) {
        const int kc = idx >> 11, rem = idx & 2047;
        const int col = rem >> 2, p = rem & 3;
        const int k0 = kc * 8 + p, k1 = k0 + 4;
        float v0 = (k0 < F_IN) ? W1[k0 * K_HID + col] : ((k0 == F_IN) ? b1[col] : 0.0f);
        float v1 = (k1 < F_IN) ? W1[k1 * K_HID + col] : ((k1 == F_IN) ? b1[col] : 0.0f);
        float2 fv;
        fv.x = __uint_as_float(tf32r(v0));
        fv.y = __uint_as_float(tf32r(v1));
        Bsm[idx] = fv;
    }
    // --- stage per-column constants (feedback weights + W2), packed per col-pair ---
    for (int col = tid; col < K_HID; col += NTH) {
        const int p = col >> 1, s = col & 1;
        cps[p * 8 + 0 + s] = W1[29 * K_HID + col];
        cps[p * 8 + 2 + s] = W1[30 * K_HID + col];
        cps[p * 8 + 4 + s] = W1[31 * K_HID + col];
        cps[p * 8 + 6 + s] = W2[col];
    }
    __syncthreads();

    // --- per-thread row bindings (warp owns rows w*16 .. w*16+15) ---
    const int rowGA = blockIdx.x * BTILE + w * 16 + lg;
    const int rowGB = rowGA + 8;
    const float* __restrict__ pA = X + (size_t)rowGA * TF_STR;
    const float* __restrict__ pB = X + (size_t)rowGB * TF_STR;
    float* __restrict__ outA = out + (size_t)rowGA * T_HOR;
    float* __restrict__ outB = out + (size_t)rowGB * T_HOR;

    float f0a = y0[rowGA * 3 + 0], f1a = y0[rowGA * 3 + 1], f2a = y0[rowGA * 3 + 2];
    float f0b = y0[rowGB * 3 + 0], f1b = y0[rowGB * 3 + 1], f2b = y0[rowGB * 3 + 2];
    const float b2v = b2[0];

    ull f0ap, f1ap, f2ap, f0bp, f1bp, f2bp;
    PACK2(f0ap, f0a, f0a); PACK2(f1ap, f1a, f1a); PACK2(f2ap, f2a, f2a);
    PACK2(f0bp, f0b, f0b); PACK2(f1bp, f1b, f1b); PACK2(f2bp, f2b, f2b);

    uint32_t aC[16], aN[16];
    loadA(aC, pA, pB, 0, lq, true);

    for (int t = 0; t < T_HOR; ++t) {
        // prefetch next step's A fragments (off the critical path)
        loadA(aN, pA, pB, t + 1, lq, (t + 1) < T_HOR);

        ull dotLo, dotHi;
        PACK2(dotLo, 0.0f, 0.0f);
        PACK2(dotHi, 0.0f, 0.0f);

        #pragma unroll 4
        for (int nt = 0; nt < 64; ++nt) {
            float d0 = 0.f, d1 = 0.f, d2 = 0.f, d3 = 0.f;
            #pragma unroll
            for (int kc = 0; kc < 4; ++kc) {
                const float2 bb = Bsm[kc * 2048 + nt * 32 + lane];
                MMA_TF32(d0, d1, d2, d3,
                         aC[kc * 4 + 0], aC[kc * 4 + 1], aC[kc * 4 + 2], aC[kc * 4 + 3],
                         __float_as_uint(bb.x), __float_as_uint(bb.y));
            }
            // epilogue on this 2x2 accum fragment: cols (c0,c1) = nt*8 + 2*lq (+1)
            const int pidx = nt * 4 + lq;
            const float4 q0 = cp4[2 * pidx + 0];  // wf0[c0],wf0[c1],wf1[c0],wf1[c1]
            const float4 q1 = cp4[2 * pidx + 1];  // wf2[c0],wf2[c1],w2[c0], w2[c1]
            ull zlo, zhi, wp;
            PACK2(zlo, d0, d1);
            PACK2(zhi, d2, d3);
            PACK2(wp, q0.x, q0.y); FMA2(zlo, wp, f0ap, zlo); FMA2(zhi, wp, f0bp, zhi);
            PACK2(wp, q0.z, q0.w); FMA2(zlo, wp, f1ap, zlo); FMA2(zhi, wp, f1bp, zhi);
            PACK2(wp, q1.x, q1.y); FMA2(zlo, wp, f2ap, zlo); FMA2(zhi, wp, f2bp, zhi);
            uint32_t u0, u1, u2, u3;
            UNPACK2(u0, u1, zlo);
            UNPACK2(u2, u3, zhi);
            const float h0 = fast_tanh(__uint_as_float(u0));
            const float h1 = fast_tanh(__uint_as_float(u1));
            const float h2 = fast_tanh(__uint_as_float(u2));
            const float h3 = fast_tanh(__uint_as_float(u3));
            ull hlo, hhi;
            PACK2(hlo, h0, h1);
            PACK2(hhi, h2, h3);
            PACK2(wp, q1.z, q1.w);
            FMA2(dotLo, hlo, wp, dotLo);
            FMA2(dotHi, hhi, wp, dotHi);
        }

        // reduce dot over the quad (cols) -> pred for rows rA and rA+8
        uint32_t s0, s1;
        UNPACK2(s0, s1, dotLo);
        float sLo = __uint_as_float(s0) + __uint_as_float(s1);
        UNPACK2(s0, s1, dotHi);
        float sHi = __uint_as_float(s0) + __uint_as_float(s1);
        sLo += __shfl_xor_sync(0xffffffffu, sLo, 1);
        sLo += __shfl_xor_sync(0xffffffffu, sLo, 2);
        sHi += __shfl_xor_sync(0xffffffffu, sHi, 1);
        sHi += __shfl_xor_sync(0xffffffffu, sHi, 2);
        const float predLo = sLo + b2v;
        const float predHi = sHi + b2v;
        if (lq == 0) {
            outA[t] = predLo;
            outB[t] = predHi;
        }
        // shift feedback: fb2 <- fb1 <- fb0 <- pred
        f2a = f1a; f1a = f0a; f0a = predLo;
        f2b = f1b; f1b = f0b; f0b = predHi;
        PACK2(f0ap, f0a, f0a); PACK2(f1ap, f1a, f1a); PACK2(f2ap, f2a, f2a);
        PACK2(f0bp, f0b, f0b); PACK2(f1bp, f1b, f1b); PACK2(f2bp, f2b, f2b);

        #pragma unroll
        for (int i = 0; i < 16; ++i) aC[i] = aN[i];
    }
}

extern "C" void kernel_launch(void* const* d_in, const int* in_sizes, int n_in,
                              void* d_out, int out_size) {
    const float* X  = (const float*)d_in[0];
    const float* y0 = (const float*)d_in[1];
    const float* W1 = (const float*)d_in[2];
    const float* b1 = (const float*)d_in[3];
    const float* W2 = (const float*)d_in[4];
    const float* b2 = (const float*)d_in[5];
    float* out = (float*)d_out;
    (void)in_sizes; (void)n_in; (void)out_size;

    cudaFuncSetAttribute(narx_kernel, cudaFuncAttributeMaxDynamicSharedMemorySize, SM_TOTAL);
    narx_kernel<<<NCTAS, NTH, SM_TOTAL>>>(X, y0, W1, b1, W2, b2, out);
}

// round 3
// speedup vs baseline: 1.3595x; 1.3595x over previous
#include <cuda_runtime.h>
#include <cstdint>

// ---------------- problem constants ----------------
#define B_TOT   16384
#define T_HOR   128
#define F_IN    29
#define K_HID   512
#define BTILE   128
#define NTH     512
#define NCTAS   (B_TOT / BTILE)     // 128, exact
#define TF_STR  (T_HOR * F_IN)      // 3712 floats per batch row

// ---------------- shared memory layout ----------------
// Bsm: 4 k-chunks x 512 cols x 4 pairs of float2 = 8192 float2 = 64KB
// cps: 256 col-pairs x 8 floats (wf0,wf0',wf1,wf1',wf2,wf2',w2,w2') = 8KB
// part: double-buffered 2 x (2 halves x 128 rows) floats = 2KB
#define SM_B_F2    8192
#define SM_CP_OFF  (SM_B_F2 * 8)                  // 65536
#define SM_PART_OFF (SM_CP_OFF + 8192)            // 73728
#define SM_TOTAL   (SM_PART_OFF + 2 * 256 * 4)    // 75776 bytes

typedef unsigned long long ull;

static __device__ __forceinline__ uint32_t tf32r(float x) {
    uint32_t r;
    asm("cvt.rna.tf32.f32 %0, %1;" : "=r"(r) : "f"(x));
    return r;
}

// tanh(z) = 1 - 2/(1 + e^{2z});  e^{2z} = 2^{z * 2*log2(e)}.  ~1e-6 accurate.
static __device__ __forceinline__ float fast_tanh(float z) {
    float e, r;
    asm("ex2.approx.f32 %0, %1;" : "=f"(e) : "f"(z * 2.8853900817779268f));
    asm("rcp.approx.f32 %0, %1;" : "=f"(r) : "f"(e + 1.0f));
    return fmaf(-2.0f, r, 1.0f);
}

#define PACK2(d, lo, hi) \
    asm("mov.b64 %0, {%1, %2};" : "=l"(d) : "r"(__float_as_uint(lo)), "r"(__float_as_uint(hi)))
#define UNPACK2(lo, hi, s) \
    asm("mov.b64 {%0, %1}, %2;" : "=r"(lo), "=r"(hi) : "l"(s))
#define FMA2(d, a, b, c) \
    asm("fma.rn.f32x2 %0, %1, %2, %3;" : "=l"(d) : "l"(a), "l"(b), "l"(c))

#define MMA_TF32(d0, d1, d2, d3, a0, a1, a2, a3, b0, b1)                       \
    asm volatile(                                                              \
        "mma.sync.aligned.m16n8k8.row.col.f32.tf32.tf32.f32 "                  \
        "{%0,%1,%2,%3}, {%4,%5,%6,%7}, {%8,%9}, {%0,%1,%2,%3};"                \
        : "+f"(d0), "+f"(d1), "+f"(d2), "+f"(d3)                               \
        : "r"(a0), "r"(a1), "r"(a2), "r"(a3), "r"(b0), "r"(b1))

// Load the A fragments (16 tf32 regs) for time step t.
// Rows: rA and rA+8 within the warp tile. Cols: kc*8 + lq, kc*8 + lq + 4.
// Col 29 = 1.0 (bias folded into the GEMM), cols 30/31 = 0.
static __device__ __forceinline__ void loadA(uint32_t a[16], const float* __restrict__ pA,
                                             const float* __restrict__ pB, int t, int lq,
                                             bool valid) {
    if (!valid) {
        #pragma unroll
        for (int i = 0; i < 16; ++i) a[i] = 0u;
        return;
    }
    const float* xA = pA + t * F_IN;
    const float* xB = pB + t * F_IN;
    #pragma unroll
    for (int kc = 0; kc < 4; ++kc) {
        const int c0 = kc * 8 + lq;          // <= 27, always a real X column
        a[kc * 4 + 0] = tf32r(__ldg(xA + c0));
        a[kc * 4 + 1] = tf32r(__ldg(xB + c0));
        if (kc < 3) {
            const int c1 = c0 + 4;           // <= 23
            a[kc * 4 + 2] = tf32r(__ldg(xA + c1));
            a[kc * 4 + 3] = tf32r(__ldg(xB + c1));
        } else {
            const int c1 = c0 + 4;           // 28..31
            float vA, vB;
            if (c1 < F_IN)       { vA = __ldg(xA + c1); vB = __ldg(xB + c1); }
            else if (c1 == F_IN) { vA = 1.0f; vB = 1.0f; }
            else                 { vA = 0.0f; vB = 0.0f; }
            a[14] = tf32r(vA);
            a[15] = tf32r(vB);
        }
    }
}

__global__ void __launch_bounds__(NTH, 1)
narx_kernel(const float* __restrict__ X, const float* __restrict__ y0,
            const float* __restrict__ W1, const float* __restrict__ b1,
            const float* __restrict__ W2, const float* __restrict__ b2,
            float* __restrict__ out)
{
    extern __shared__ char smem[];
    float2* __restrict__ Bsm = (float2*)smem;
    float*  __restrict__ cps = (float*)(smem + SM_CP_OFF);
    float*  __restrict__ part = (float*)(smem + SM_PART_OFF);
    const float4* __restrict__ cp4 = (const float4*)cps;

    const int tid  = threadIdx.x;
    const int w    = tid >> 5;
    const int lane = tid & 31;
    const int lq   = lane & 3;       // quad lane (k / col-pair selector)
    const int lg   = lane >> 2;      // group (row selector)
    const int h    = w >> 3;         // column half: 0 -> cols 0-255, 1 -> 256-511
    const int g    = w & 7;          // row group: rows g*16 .. g*16+15

    // --- stage B operand: W1 rows 0-28, row 29 = b1 (bias), rows 30/31 = 0 ---
    // float2 idx = kc*2048 + col*4 + p  holds (W[kc*8+p][col], W[kc*8+p+4][col]).
    for (int idx = tid; idx < SM_B_F2; idx += NTH) {
        const int kc = idx >> 11, rem = idx & 2047;
        const int col = rem >> 2, p = rem & 3;
        const int k0 = kc * 8 + p, k1 = k0 + 4;
        float v0 = (k0 < F_IN) ? W1[k0 * K_HID + col] : ((k0 == F_IN) ? b1[col] : 0.0f);
        float v1 = (k1 < F_IN) ? W1[k1 * K_HID + col] : ((k1 == F_IN) ? b1[col] : 0.0f);
        float2 fv;
        fv.x = __uint_as_float(tf32r(v0));
        fv.y = __uint_as_float(tf32r(v1));
        Bsm[idx] = fv;
    }
    // --- per-column constants (feedback weights + W2), packed per col-pair ---
    for (int col = tid; col < K_HID; col += NTH) {
        const int p = col >> 1, s = col & 1;
        cps[p * 8 + 0 + s] = W1[29 * K_HID + col];
        cps[p * 8 + 2 + s] = W1[30 * K_HID + col];
        cps[p * 8 + 4 + s] = W1[31 * K_HID + col];
        cps[p * 8 + 6 + s] = W2[col];
    }
    __syncthreads();

    // --- per-thread row bindings ---
    const int rowLA = g * 16 + lg;          // local rows within the 128-row tile
    const int rowLB = rowLA + 8;
    const int rowGA = blockIdx.x * BTILE + rowLA;
    const int rowGB = rowGA + 8;
    const float* __restrict__ pA = X + (size_t)rowGA * TF_STR;
    const float* __restrict__ pB = X + (size_t)rowGB * TF_STR;
    float* __restrict__ outA = out + (size_t)rowGA * T_HOR;
    float* __restrict__ outB = out + (size_t)rowGB * T_HOR;

    float f0a = y0[rowGA * 3 + 0], f1a = y0[rowGA * 3 + 1], f2a = y0[rowGA * 3 + 2];
    float f0b = y0[rowGB * 3 + 0], f1b = y0[rowGB * 3 + 1], f2b = y0[rowGB * 3 + 2];
    const float b2v = b2[0];

    ull f0ap, f1ap, f2ap, f0bp, f1bp, f2bp;
    PACK2(f0ap, f0a, f0a); PACK2(f1ap, f1a, f1a); PACK2(f2ap, f2a, f2a);
    PACK2(f0bp, f0b, f0b); PACK2(f1bp, f1b, f1b); PACK2(f2bp, f2b, f2b);

    uint32_t aC[16], aN[16];
    loadA(aC, pA, pB, 0, lq, true);

    const int ntOfs = h * 32;               // this warp's n-tile offset

    for (int t = 0; t < T_HOR; ++t) {
        // prefetch next step's A fragments (off the critical path)
        loadA(aN, pA, pB, t + 1, lq, (t + 1) < T_HOR);

        ull dotLo, dotHi;
        PACK2(dotLo, 0.0f, 0.0f);
        PACK2(dotHi, 0.0f, 0.0f);

        #pragma unroll 4
        for (int nt = 0; nt < 32; ++nt) {
            const int ntg = ntOfs + nt;      // global n-tile (0..63)
            float d0 = 0.f, d1 = 0.f, d2 = 0.f, d3 = 0.f;
            #pragma unroll
            for (int kc = 0; kc < 4; ++kc) {
                const float2 bb = Bsm[kc * 2048 + ntg * 32 + lane];
                MMA_TF32(d0, d1, d2, d3,
                         aC[kc * 4 + 0], aC[kc * 4 + 1], aC[kc * 4 + 2], aC[kc * 4 + 3],
                         __float_as_uint(bb.x), __float_as_uint(bb.y));
            }
            // epilogue on this 2x2 accum fragment: cols (c0,c1) = ntg*8 + 2*lq (+1)
            const int pidx = ntg * 4 + lq;
            const float4 q0 = cp4[2 * pidx + 0];  // wf0[c0],wf0[c1],wf1[c0],wf1[c1]
            const float4 q1 = cp4[2 * pidx + 1];  // wf2[c0],wf2[c1],w2[c0], w2[c1]
            ull zlo, zhi, wp;
            PACK2(zlo, d0, d1);
            PACK2(zhi, d2, d3);
            PACK2(wp, q0.x, q0.y); FMA2(zlo, wp, f0ap, zlo); FMA2(zhi, wp, f0bp, zhi);
            PACK2(wp, q0.z, q0.w); FMA2(zlo, wp, f1ap, zlo); FMA2(zhi, wp, f1bp, zhi);
            PACK2(wp, q1.x, q1.y); FMA2(zlo, wp, f2ap, zlo); FMA2(zhi, wp, f2bp, zhi);
            uint32_t u0, u1, u2, u3;
            UNPACK2(u0, u1, zlo);
            UNPACK2(u2, u3, zhi);
            const float h0 = fast_tanh(__uint_as_float(u0));
            const float h1 = fast_tanh(__uint_as_float(u1));
            const float h2 = fast_tanh(__uint_as_float(u2));
            const float h3 = fast_tanh(__uint_as_float(u3));
            ull hlo, hhi;
            PACK2(hlo, h0, h1);
            PACK2(hhi, h2, h3);
            PACK2(wp, q1.z, q1.w);
            FMA2(dotLo, hlo, wp, dotLo);
            FMA2(dotHi, hhi, wp, dotHi);
        }

        // reduce dot over the quad (cols) -> this half's partial for rows rA, rA+8
        uint32_t s0, s1;
        UNPACK2(s0, s1, dotLo);
        float sLo = __uint_as_float(s0) + __uint_as_float(s1);
        UNPACK2(s0, s1, dotHi);
        float sHi = __uint_as_float(s0) + __uint_as_float(s1);
        sLo += __shfl_xor_sync(0xffffffffu, sLo, 1);
        sLo += __shfl_xor_sync(0xffffffffu, sLo, 2);
        sHi += __shfl_xor_sync(0xffffffffu, sHi, 1);
        sHi += __shfl_xor_sync(0xffffffffu, sHi, 2);

        // cross-half combine via double-buffered SMEM partials + one barrier
        float* pbuf = part + (t & 1) * 256;
        if (lq == 0) {
            pbuf[h * 128 + rowLA] = sLo;
            pbuf[h * 128 + rowLB] = sHi;
        }
        __syncthreads();
        const float predLo = pbuf[rowLA] + pbuf[128 + rowLA] + b2v;
        const float predHi = pbuf[rowLB] + pbuf[128 + rowLB] + b2v;
        if (h == 0 && lq == 0) {
            outA[t] = predLo;
            outB[t] = predHi;
        }
        // shift feedback: fb2 <- fb1 <- fb0 <- pred
        f2a = f1a; f1a = f0a; f0a = predLo;
        f2b = f1b; f1b = f0b; f0b = predHi;
        PACK2(f0ap, f0a, f0a); PACK2(f1ap, f1a, f1a); PACK2(f2ap, f2a, f2a);
        PACK2(f0bp, f0b, f0b); PACK2(f1bp, f1b, f1b); PACK2(f2bp, f2b, f2b);

        #pragma unroll
        for (int i = 0; i < 16; ++i) aC[i] = aN[i];
    }
}

extern "C" void kernel_launch(void* const* d_in, const int* in_sizes, int n_in,
                              void* d_out, int out_size) {
    const float* X  = (const float*)d_in[0];
    const float* y0 = (const float*)d_in[1];
    const float* W1 = (const float*)d_in[2];
    const float* b1 = (const float*)d_in[3];
    const float* W2 = (const float*)d_in[4];
    const float* b2 = (const float*)d_in[5];
    float* out = (float*)d_out;
    (void)in_sizes; (void)n_in; (void)out_size;

    cudaFuncSetAttribute(narx_kernel, cudaFuncAttributeMaxDynamicSharedMemorySize, SM_TOTAL);
    narx_kernel<<<NCTAS, NTH, SM_TOTAL>>>(X, y0, W1, b1, W2, b2, out);
}